// round 12
// baseline (speedup 1.0000x reference)
#include <cuda_runtime.h>
#include <cuda_bf16.h>

#define NB      65536
#define THREADS 192
#define SPB     32

// ---- shared memory layout (u32/f32 offsets) ----
#define OFF_WA    0       // [10][32] f32
#define OFF_WB    320     // [10][32] f32
#define OFF_W2P   640     // [15][20] u32 bf16x2: (W2[2lp][o], W2[2lp+1][o])
#define OFF_SB2P  940     // [20] u32 bf16x2: (sb2[o], 0)
#define OFF_W3    960     // [20] f32
#define OFF_CW1   980     // [6][20]
#define OFF_CB1   1100    // [6][20]
#define OFF_CW2   1220    // [6][20][12]
#define OFF_CB2   2660    // [6][12]
#define OFF_OUTW  2732    // [80]
#define OFF_MISC  2812    // [0]=sb3,[1]=out_b
#define OFF_PETA  2814    // [192]
#define OFF_C1    3008    // [78][16] u32 bf16x2 (16B aligned)
#define OFF_AB    4256    // [32][388] u32; rows A0..A11,B0..B11 of 16 u32
#define AB_STRIDE 388
#define SMEM_U32  (OFF_AB + SPB * AB_STRIDE)   // 16672 u32 = 66688 B

extern __shared__ float smem[];

__device__ __forceinline__ unsigned f2bf(float a, float b) {
    __nv_bfloat162 h = __floats2bfloat162_rn(a, b);
    return *reinterpret_cast<unsigned*>(&h);
}
__device__ __forceinline__ __nv_bfloat162 uib(unsigned u) {
    return *reinterpret_cast<__nv_bfloat162*>(&u);
}
__device__ __forceinline__ unsigned biu(__nv_bfloat162 h) {
    return *reinterpret_cast<unsigned*>(&h);
}
__device__ __forceinline__ unsigned swap16(unsigned u) {
    unsigned r; asm("prmt.b32 %0, %1, %1, 0x1032;" : "=r"(r) : "r"(u)); return r;
}

__global__ void __launch_bounds__(THREADS, 3)
pin_kernel(const float* __restrict__ x_cont, const int* __restrict__ x_cat,
           const float* __restrict__ exposure,
           const float* __restrict__ cont_W1, const float* __restrict__ cont_b1,
           const float* __restrict__ cont_W2, const float* __restrict__ cont_b2,
           const float* __restrict__ cat_tables, const float* __restrict__ tokens,
           const float* __restrict__ sW1, const float* __restrict__ sb1,
           const float* __restrict__ sW2, const float* __restrict__ sb2,
           const float* __restrict__ sW3, const float* __restrict__ sb3,
           const float* __restrict__ out_w, const float* __restrict__ out_b,
           float* __restrict__ out)
{
    unsigned* smemu = (unsigned*)smem;
    const int tid  = threadIdx.x;
    const int lane = tid & 31;
    const int sub  = tid >> 5;

    // ---------------- staging ----------------
    for (int i = tid; i < 320; i += THREADS) {
        int d = i >> 5, l = i & 31;
        smem[OFF_WA + i] = (l < 30) ? sW1[d * 30 + l] : 0.f;
        smem[OFF_WB + i] = (l < 30) ? sW1[(10 + d) * 30 + l] : 0.f;
    }
    for (int i = tid; i < 300; i += THREADS) {      // W2 pair-packed
        int lp = i / 20, o = i % 20;
        smemu[OFF_W2P + i] = f2bf(sW2[(2 * lp) * 20 + o], sW2[(2 * lp + 1) * 20 + o]);
    }
    for (int i = tid; i < 20; i += THREADS) {
        smemu[OFF_SB2P + i] = f2bf(sb2[i], 0.f);
        smem[OFF_W3 + i] = sW3[i];
    }
    for (int i = tid; i < 120; i += THREADS) {
        smem[OFF_CW1 + i] = cont_W1[i];
        smem[OFF_CB1 + i] = cont_b1[i];
    }
    for (int i = tid; i < 1200; i += THREADS) {
        int c = i / 200, r = i % 200, h = r / 10, d = r % 10;
        smem[OFF_CW2 + (c * 20 + h) * 12 + d] = cont_W2[i];
    }
    for (int i = tid; i < 60; i += THREADS)
        smem[OFF_CB2 + (i / 10) * 12 + (i % 10)] = cont_b2[i];
    for (int i = tid; i < 78; i += THREADS) smem[OFF_OUTW + i] = out_w[i];
    if (tid == 0) { smem[OFF_MISC + 0] = sb3[0]; smem[OFF_MISC + 1] = out_b[0]; }
    for (int i = tid; i < 78 * 16; i += THREADS) {
        int p = i >> 4, lp = i & 15;
        int l0 = lp * 2, l1 = l0 + 1;
        float v0 = 0.f, v1 = 0.f;
        if (l0 < 30) {
            v0 = sb1[l0];
#pragma unroll
            for (int d = 0; d < 10; ++d)
                v0 = fmaf(tokens[p * 10 + d], sW1[(20 + d) * 30 + l0], v0);
        }
        if (l1 < 30) {
            v1 = sb1[l1];
#pragma unroll
            for (int d = 0; d < 10; ++d)
                v1 = fmaf(tokens[p * 10 + d], sW1[(20 + d) * 30 + l1], v1);
        }
        smemu[OFF_C1 + i] = f2bf(v0, v1);
    }
    __syncthreads();

    // ---------------- per-sample feature + projection (f32) ----------------
    const int b = blockIdx.x * SPB + lane;
    unsigned* myAB = smemu + OFF_AB + lane * AB_STRIDE;

    float e[10];
    {
        int c = sub;
        float x = x_cont[b * 6 + c];
#pragma unroll
        for (int d = 0; d < 10; ++d) e[d] = smem[OFF_CB2 + c * 12 + d];
#pragma unroll
        for (int h = 0; h < 20; ++h) {
            float hv = fmaxf(fmaf(x, smem[OFF_CW1 + c * 20 + h],
                                  smem[OFF_CB1 + c * 20 + h]), 0.f);
#pragma unroll
            for (int d = 0; d < 10; ++d)
                e[d] = fmaf(hv, smem[OFF_CW2 + (c * 20 + h) * 12 + d], e[d]);
        }
    }
#pragma unroll 1
    for (int proj = 0; proj < 2; ++proj) {
        const float* W = smem + (proj ? OFF_WB : OFF_WA);
        float acc[32];
#pragma unroll
        for (int l = 0; l < 32; ++l) acc[l] = 0.f;
#pragma unroll
        for (int d = 0; d < 10; ++d)
#pragma unroll
            for (int l = 0; l < 32; ++l)
                acc[l] = fmaf(e[d], W[d * 32 + l], acc[l]);
        unsigned* dst = myAB + (proj ? (12 + sub) : sub) * 16;
#pragma unroll
        for (int i = 0; i < 16; ++i) dst[i] = f2bf(acc[2 * i], acc[2 * i + 1]);
    }
    {
        int c = sub;
        int idx = x_cat[b * 6 + c];
        const float2* row = (const float2*)(cat_tables + (size_t)(c * 100 + idx) * 10);
#pragma unroll
        for (int d = 0; d < 5; ++d) { float2 v = row[d]; e[2*d] = v.x; e[2*d+1] = v.y; }
    }
#pragma unroll 1
    for (int proj = 0; proj < 2; ++proj) {
        const float* W = smem + (proj ? OFF_WB : OFF_WA);
        float acc[32];
#pragma unroll
        for (int l = 0; l < 32; ++l) acc[l] = 0.f;
#pragma unroll
        for (int d = 0; d < 10; ++d)
#pragma unroll
            for (int l = 0; l < 32; ++l)
                acc[l] = fmaf(e[d], W[d * 32 + l], acc[l]);
        unsigned* dst = myAB + (proj ? (18 + sub) : (6 + sub)) * 16;
#pragma unroll
        for (int i = 0; i < 16; ++i) dst[i] = f2bf(acc[2 * i], acc[2 * i + 1]);
    }
    __syncthreads();

    // ---------------- pair loop: rows {sub, 11-sub} = 13 pairs ----------------
    const float raw_bias = smem[OFF_MISC + 0];
    const __nv_bfloat162 z2 = __floats2bfloat162_rn(0.f, 0.f);
    float eta = 0.f;

#define H1STEP(idx, ua, ub, uc)                                         \
    h1u[idx] = biu(__hmax2(__hadd2(__hadd2(uib(ua), uib(ub)), uib(uc)), z2))

#pragma unroll 1
    for (int r = 0; r < 2; ++r) {
        const int j = r ? (11 - sub) : sub;
        const int pbase = (j * (25 - j)) >> 1;
        const uint4* Aj = (const uint4*)(myAB + j * 16);

#pragma unroll 1
        for (int k = j; k < 12; ++k) {
            const int p = pbase + (k - j);
            const uint4* Bk = (const uint4*)(myAB + (12 + k) * 16);
            const uint4* Cp = (const uint4*)(smemu + OFF_C1 + p * 16);

            // ---- h1 (30 vals as 15 bf16x2) ----
            unsigned h1u[15];
            {
                uint4 a = Aj[0], bb = Bk[0], c = Cp[0];
                H1STEP(0, a.x, bb.x, c.x); H1STEP(1, a.y, bb.y, c.y);
                H1STEP(2, a.z, bb.z, c.z); H1STEP(3, a.w, bb.w, c.w);
            }
            {
                uint4 a = Aj[1], bb = Bk[1], c = Cp[1];
                H1STEP(4, a.x, bb.x, c.x); H1STEP(5, a.y, bb.y, c.y);
                H1STEP(6, a.z, bb.z, c.z); H1STEP(7, a.w, bb.w, c.w);
            }
            {
                uint4 a = Aj[2], bb = Bk[2], c = Cp[2];
                H1STEP(8, a.x, bb.x, c.x); H1STEP(9, a.y, bb.y, c.y);
                H1STEP(10, a.z, bb.z, c.z); H1STEP(11, a.w, bb.w, c.w);
            }
            {
                uint4 a = Aj[3], bb = Bk[3], c = Cp[3];
                H1STEP(12, a.x, bb.x, c.x); H1STEP(13, a.y, bb.y, c.y);
                H1STEP(14, a.z, bb.z, c.z);
            }

            // ---- acc2[o]: lo = even-l partial, hi = odd-l partial ----
            __nv_bfloat162 acc2[20];
            {
                const uint4* sbp = (const uint4*)(smemu + OFF_SB2P);
                uint4 s0 = sbp[0], s1 = sbp[1], s2 = sbp[2], s3 = sbp[3], s4 = sbp[4];
                acc2[0]=uib(s0.x); acc2[1]=uib(s0.y); acc2[2]=uib(s0.z); acc2[3]=uib(s0.w);
                acc2[4]=uib(s1.x); acc2[5]=uib(s1.y); acc2[6]=uib(s1.z); acc2[7]=uib(s1.w);
                acc2[8]=uib(s2.x); acc2[9]=uib(s2.y); acc2[10]=uib(s2.z); acc2[11]=uib(s2.w);
                acc2[12]=uib(s3.x); acc2[13]=uib(s3.y); acc2[14]=uib(s3.z); acc2[15]=uib(s3.w);
                acc2[16]=uib(s4.x); acc2[17]=uib(s4.y); acc2[18]=uib(s4.z); acc2[19]=uib(s4.w);
            }

#pragma unroll
            for (int lp = 0; lp < 15; ++lp) {
                __nv_bfloat162 hv = uib(h1u[lp]);
                const uint4* wr = (const uint4*)(smemu + OFF_W2P + lp * 20);
                uint4 w0 = wr[0], w1 = wr[1], w2u = wr[2], w3u = wr[3], w4 = wr[4];
                acc2[0]  = __hfma2(hv, uib(w0.x), acc2[0]);
                acc2[1]  = __hfma2(hv, uib(w0.y), acc2[1]);
                acc2[2]  = __hfma2(hv, uib(w0.z), acc2[2]);
                acc2[3]  = __hfma2(hv, uib(w0.w), acc2[3]);
                acc2[4]  = __hfma2(hv, uib(w1.x), acc2[4]);
                acc2[5]  = __hfma2(hv, uib(w1.y), acc2[5]);
                acc2[6]  = __hfma2(hv, uib(w1.z), acc2[6]);
                acc2[7]  = __hfma2(hv, uib(w1.w), acc2[7]);
                acc2[8]  = __hfma2(hv, uib(w2u.x), acc2[8]);
                acc2[9]  = __hfma2(hv, uib(w2u.y), acc2[9]);
                acc2[10] = __hfma2(hv, uib(w2u.z), acc2[10]);
                acc2[11] = __hfma2(hv, uib(w2u.w), acc2[11]);
                acc2[12] = __hfma2(hv, uib(w3u.x), acc2[12]);
                acc2[13] = __hfma2(hv, uib(w3u.y), acc2[13]);
                acc2[14] = __hfma2(hv, uib(w3u.z), acc2[14]);
                acc2[15] = __hfma2(hv, uib(w3u.w), acc2[15]);
                acc2[16] = __hfma2(hv, uib(w4.x), acc2[16]);
                acc2[17] = __hfma2(hv, uib(w4.y), acc2[17]);
                acc2[18] = __hfma2(hv, uib(w4.z), acc2[18]);
                acc2[19] = __hfma2(hv, uib(w4.w), acc2[19]);
            }

            // ---- tail: h2[o] = lo+hi; raw += relu(h2)*w3 ----
            float raw = raw_bias;
            {
                const float4* w3r = (const float4*)(smem + OFF_W3);
#pragma unroll
                for (int v = 0; v < 5; ++v) {
                    float4 w = w3r[v];
#pragma unroll
                    for (int q = 0; q < 4; ++q) {
                        int o = v * 4 + q;
                        unsigned u = biu(acc2[o]);
                        __nv_bfloat162 t = __hadd2(uib(u), uib(swap16(u)));
                        float f = __uint_as_float(biu(t) & 0xFFFF0000u);
                        float wq = (q==0)?w.x:(q==1)?w.y:(q==2)?w.z:w.w;
                        raw = fmaf(fmaxf(f, 0.f), wq, raw);
                    }
                }
            }
            float ht = fminf(fmaxf(raw * (1.f/6.f) + 0.5f, 0.f), 1.f) - 0.5f;
            eta = fmaf(smem[OFF_OUTW + p], ht, eta);
        }
    }

    smem[OFF_PETA + tid] = eta;
    __syncthreads();
    if (tid < 32) {
        float esum = 0.f;
#pragma unroll
        for (int s = 0; s < 6; ++s) esum += smem[OFF_PETA + tid + 32 * s];
        esum += smem[OFF_MISC + 1];
        esum = fminf(fmaxf(esum, -20.f), 20.f);
        out[b] = __expf(esum) * exposure[b];
    }
}

extern "C" void kernel_launch(void* const* d_in, const int* in_sizes, int n_in,
                              void* d_out, int out_size)
{
    (void)in_sizes; (void)n_in; (void)out_size;
    size_t shmem = SMEM_U32 * 4;
    cudaFuncSetAttribute(pin_kernel, cudaFuncAttributeMaxDynamicSharedMemorySize,
                         (int)shmem);
    pin_kernel<<<NB / SPB, THREADS, shmem>>>(
        (const float*)d_in[0],  (const int*)d_in[1],   (const float*)d_in[2],
        (const float*)d_in[3],  (const float*)d_in[4], (const float*)d_in[5],
        (const float*)d_in[6],  (const float*)d_in[7], (const float*)d_in[8],
        (const float*)d_in[9],  (const float*)d_in[10],(const float*)d_in[11],
        (const float*)d_in[12], (const float*)d_in[13],(const float*)d_in[14],
        (const float*)d_in[15], (const float*)d_in[16],
        (float*)d_out);
}

// round 13
// speedup vs baseline: 2.4410x; 2.4410x over previous
#include <cuda_runtime.h>
#include <cuda_bf16.h>

#define NB      65536
#define THREADS 192
#define SPB     32

// ---- shared memory layout (u32/f32 offsets) ----
#define OFF_WA    0       // [10][32] f32
#define OFF_WB    320     // [10][32] f32
#define OFF_W2P   640     // [15][20] u32 bf16x2: (W2[2lp][o], W2[2lp+1][o])
#define OFF_SB2P  940     // [20] u32 bf16x2: (sb2[o], 0)
#define OFF_W3    960     // [20] f32
#define OFF_CW1   980     // [6][20]
#define OFF_CB1   1100    // [6][20]
#define OFF_CW2   1220    // [6][20][12]
#define OFF_CB2   2660    // [6][12]
#define OFF_OUTW  2732    // [80]
#define OFF_MISC  2812    // [0]=sb3,[1]=out_b
#define OFF_PETA  2814    // [192]
#define OFF_C1    3008    // [78][16] u32 bf16x2 (16B aligned)
#define OFF_AB    4256    // [32][388] u32; rows A0..A11,B0..B11 of 16 u32
#define AB_STRIDE 388
#define SMEM_U32  (OFF_AB + SPB * AB_STRIDE)   // 16672 u32 = 66688 B

extern __shared__ float smem[];

__device__ __forceinline__ unsigned f2bf(float a, float b) {
    __nv_bfloat162 h = __floats2bfloat162_rn(a, b);
    return *reinterpret_cast<unsigned*>(&h);
}
__device__ __forceinline__ __nv_bfloat162 uib(unsigned u) {
    return *reinterpret_cast<__nv_bfloat162*>(&u);
}
__device__ __forceinline__ unsigned biu(__nv_bfloat162 h) {
    return *reinterpret_cast<unsigned*>(&h);
}
__device__ __forceinline__ unsigned swap16(unsigned u) {
    unsigned r; asm("prmt.b32 %0, %1, %1, 0x1032;" : "=r"(r) : "r"(u)); return r;
}

__global__ void __launch_bounds__(THREADS, 2)
pin_kernel(const float* __restrict__ x_cont, const int* __restrict__ x_cat,
           const float* __restrict__ exposure,
           const float* __restrict__ cont_W1, const float* __restrict__ cont_b1,
           const float* __restrict__ cont_W2, const float* __restrict__ cont_b2,
           const float* __restrict__ cat_tables, const float* __restrict__ tokens,
           const float* __restrict__ sW1, const float* __restrict__ sb1,
           const float* __restrict__ sW2, const float* __restrict__ sb2,
           const float* __restrict__ sW3, const float* __restrict__ sb3,
           const float* __restrict__ out_w, const float* __restrict__ out_b,
           float* __restrict__ out)
{
    unsigned* smemu = (unsigned*)smem;
    const int tid  = threadIdx.x;
    const int lane = tid & 31;
    const int sub  = tid >> 5;

    // ---------------- staging ----------------
    for (int i = tid; i < 320; i += THREADS) {
        int d = i >> 5, l = i & 31;
        smem[OFF_WA + i] = (l < 30) ? sW1[d * 30 + l] : 0.f;
        smem[OFF_WB + i] = (l < 30) ? sW1[(10 + d) * 30 + l] : 0.f;
    }
    for (int i = tid; i < 300; i += THREADS) {      // W2 pair-packed
        int lp = i / 20, o = i % 20;
        smemu[OFF_W2P + i] = f2bf(sW2[(2 * lp) * 20 + o], sW2[(2 * lp + 1) * 20 + o]);
    }
    for (int i = tid; i < 20; i += THREADS) {
        smemu[OFF_SB2P + i] = f2bf(sb2[i], 0.f);
        smem[OFF_W3 + i] = sW3[i];
    }
    for (int i = tid; i < 120; i += THREADS) {
        smem[OFF_CW1 + i] = cont_W1[i];
        smem[OFF_CB1 + i] = cont_b1[i];
    }
    for (int i = tid; i < 1200; i += THREADS) {
        int c = i / 200, r = i % 200, h = r / 10, d = r % 10;
        smem[OFF_CW2 + (c * 20 + h) * 12 + d] = cont_W2[i];
    }
    for (int i = tid; i < 60; i += THREADS)
        smem[OFF_CB2 + (i / 10) * 12 + (i % 10)] = cont_b2[i];
    for (int i = tid; i < 78; i += THREADS) smem[OFF_OUTW + i] = out_w[i];
    if (tid == 0) { smem[OFF_MISC + 0] = sb3[0]; smem[OFF_MISC + 1] = out_b[0]; }
    for (int i = tid; i < 78 * 16; i += THREADS) {
        int p = i >> 4, lp = i & 15;
        int l0 = lp * 2, l1 = l0 + 1;
        float v0 = 0.f, v1 = 0.f;
        if (l0 < 30) {
            v0 = sb1[l0];
#pragma unroll
            for (int d = 0; d < 10; ++d)
                v0 = fmaf(tokens[p * 10 + d], sW1[(20 + d) * 30 + l0], v0);
        }
        if (l1 < 30) {
            v1 = sb1[l1];
#pragma unroll
            for (int d = 0; d < 10; ++d)
                v1 = fmaf(tokens[p * 10 + d], sW1[(20 + d) * 30 + l1], v1);
        }
        smemu[OFF_C1 + i] = f2bf(v0, v1);
    }
    __syncthreads();

    // ---------------- per-sample feature + projection (f32) ----------------
    const int b = blockIdx.x * SPB + lane;
    unsigned* myAB = smemu + OFF_AB + lane * AB_STRIDE;

    float e[10];
    {
        int c = sub;
        float x = x_cont[b * 6 + c];
#pragma unroll
        for (int d = 0; d < 10; ++d) e[d] = smem[OFF_CB2 + c * 12 + d];
#pragma unroll
        for (int h = 0; h < 20; ++h) {
            float hv = fmaxf(fmaf(x, smem[OFF_CW1 + c * 20 + h],
                                  smem[OFF_CB1 + c * 20 + h]), 0.f);
#pragma unroll
            for (int d = 0; d < 10; ++d)
                e[d] = fmaf(hv, smem[OFF_CW2 + (c * 20 + h) * 12 + d], e[d]);
        }
    }
#pragma unroll 1
    for (int proj = 0; proj < 2; ++proj) {
        const float* W = smem + (proj ? OFF_WB : OFF_WA);
        float acc[32];
#pragma unroll
        for (int l = 0; l < 32; ++l) acc[l] = 0.f;
#pragma unroll
        for (int d = 0; d < 10; ++d)
#pragma unroll
            for (int l = 0; l < 32; ++l)
                acc[l] = fmaf(e[d], W[d * 32 + l], acc[l]);
        unsigned* dst = myAB + (proj ? (12 + sub) : sub) * 16;
#pragma unroll
        for (int i = 0; i < 16; ++i) dst[i] = f2bf(acc[2 * i], acc[2 * i + 1]);
    }
    {
        int c = sub;
        int idx = x_cat[b * 6 + c];
        const float2* row = (const float2*)(cat_tables + (size_t)(c * 100 + idx) * 10);
#pragma unroll
        for (int d = 0; d < 5; ++d) { float2 v = row[d]; e[2*d] = v.x; e[2*d+1] = v.y; }
    }
#pragma unroll 1
    for (int proj = 0; proj < 2; ++proj) {
        const float* W = smem + (proj ? OFF_WB : OFF_WA);
        float acc[32];
#pragma unroll
        for (int l = 0; l < 32; ++l) acc[l] = 0.f;
#pragma unroll
        for (int d = 0; d < 10; ++d)
#pragma unroll
            for (int l = 0; l < 32; ++l)
                acc[l] = fmaf(e[d], W[d * 32 + l], acc[l]);
        unsigned* dst = myAB + (proj ? (18 + sub) : (6 + sub)) * 16;
#pragma unroll
        for (int i = 0; i < 16; ++i) dst[i] = f2bf(acc[2 * i], acc[2 * i + 1]);
    }
    __syncthreads();

    // ---------------- pair loop: rows {sub, 11-sub} = 13 pairs ----------------
    const float raw_bias = smem[OFF_MISC + 0];
    const __nv_bfloat162 z2 = __floats2bfloat162_rn(0.f, 0.f);
    float eta = 0.f;

#define H1STEP(idx, ua, ub, uc)                                         \
    h1u[idx] = biu(__hmax2(__hadd2(__hadd2(uib(ua), uib(ub)), uib(uc)), z2))

#pragma unroll 1
    for (int r = 0; r < 2; ++r) {
        const int j = r ? (11 - sub) : sub;
        const int pbase = (j * (25 - j)) >> 1;
        const uint4* Aj = (const uint4*)(myAB + j * 16);

#pragma unroll 1
        for (int k = j; k < 12; ++k) {
            const int p = pbase + (k - j);
            const uint4* Bk = (const uint4*)(myAB + (12 + k) * 16);
            const uint4* Cp = (const uint4*)(smemu + OFF_C1 + p * 16);

            // ---- h1 (30 vals as 15 bf16x2) ----
            unsigned h1u[15];
            {
                uint4 a = Aj[0], bb = Bk[0], c = Cp[0];
                H1STEP(0, a.x, bb.x, c.x); H1STEP(1, a.y, bb.y, c.y);
                H1STEP(2, a.z, bb.z, c.z); H1STEP(3, a.w, bb.w, c.w);
            }
            {
                uint4 a = Aj[1], bb = Bk[1], c = Cp[1];
                H1STEP(4, a.x, bb.x, c.x); H1STEP(5, a.y, bb.y, c.y);
                H1STEP(6, a.z, bb.z, c.z); H1STEP(7, a.w, bb.w, c.w);
            }
            {
                uint4 a = Aj[2], bb = Bk[2], c = Cp[2];
                H1STEP(8, a.x, bb.x, c.x); H1STEP(9, a.y, bb.y, c.y);
                H1STEP(10, a.z, bb.z, c.z); H1STEP(11, a.w, bb.w, c.w);
            }
            {
                uint4 a = Aj[3], bb = Bk[3], c = Cp[3];
                H1STEP(12, a.x, bb.x, c.x); H1STEP(13, a.y, bb.y, c.y);
                H1STEP(14, a.z, bb.z, c.z);
            }

            // ---- acc2[o]: lo = even-l partial, hi = odd-l partial ----
            __nv_bfloat162 acc2[20];
            {
                const uint4* sbp = (const uint4*)(smemu + OFF_SB2P);
                uint4 s0 = sbp[0], s1 = sbp[1], s2 = sbp[2], s3 = sbp[3], s4 = sbp[4];
                acc2[0]=uib(s0.x); acc2[1]=uib(s0.y); acc2[2]=uib(s0.z); acc2[3]=uib(s0.w);
                acc2[4]=uib(s1.x); acc2[5]=uib(s1.y); acc2[6]=uib(s1.z); acc2[7]=uib(s1.w);
                acc2[8]=uib(s2.x); acc2[9]=uib(s2.y); acc2[10]=uib(s2.z); acc2[11]=uib(s2.w);
                acc2[12]=uib(s3.x); acc2[13]=uib(s3.y); acc2[14]=uib(s3.z); acc2[15]=uib(s3.w);
                acc2[16]=uib(s4.x); acc2[17]=uib(s4.y); acc2[18]=uib(s4.z); acc2[19]=uib(s4.w);
            }

#pragma unroll
            for (int lp = 0; lp < 15; ++lp) {
                __nv_bfloat162 hv = uib(h1u[lp]);
                const uint4* wr = (const uint4*)(smemu + OFF_W2P + lp * 20);
                uint4 w0 = wr[0], w1 = wr[1], w2u = wr[2], w3u = wr[3], w4 = wr[4];
                acc2[0]  = __hfma2(hv, uib(w0.x), acc2[0]);
                acc2[1]  = __hfma2(hv, uib(w0.y), acc2[1]);
                acc2[2]  = __hfma2(hv, uib(w0.z), acc2[2]);
                acc2[3]  = __hfma2(hv, uib(w0.w), acc2[3]);
                acc2[4]  = __hfma2(hv, uib(w1.x), acc2[4]);
                acc2[5]  = __hfma2(hv, uib(w1.y), acc2[5]);
                acc2[6]  = __hfma2(hv, uib(w1.z), acc2[6]);
                acc2[7]  = __hfma2(hv, uib(w1.w), acc2[7]);
                acc2[8]  = __hfma2(hv, uib(w2u.x), acc2[8]);
                acc2[9]  = __hfma2(hv, uib(w2u.y), acc2[9]);
                acc2[10] = __hfma2(hv, uib(w2u.z), acc2[10]);
                acc2[11] = __hfma2(hv, uib(w2u.w), acc2[11]);
                acc2[12] = __hfma2(hv, uib(w3u.x), acc2[12]);
                acc2[13] = __hfma2(hv, uib(w3u.y), acc2[13]);
                acc2[14] = __hfma2(hv, uib(w3u.z), acc2[14]);
                acc2[15] = __hfma2(hv, uib(w3u.w), acc2[15]);
                acc2[16] = __hfma2(hv, uib(w4.x), acc2[16]);
                acc2[17] = __hfma2(hv, uib(w4.y), acc2[17]);
                acc2[18] = __hfma2(hv, uib(w4.z), acc2[18]);
                acc2[19] = __hfma2(hv, uib(w4.w), acc2[19]);
            }

            // ---- tail: h2[o] = lo+hi; raw += relu(h2)*w3 ----
            float raw = raw_bias;
            {
                const float4* w3r = (const float4*)(smem + OFF_W3);
#pragma unroll
                for (int v = 0; v < 5; ++v) {
                    float4 w = w3r[v];
#pragma unroll
                    for (int q = 0; q < 4; ++q) {
                        int o = v * 4 + q;
                        unsigned u = biu(acc2[o]);
                        __nv_bfloat162 t = __hadd2(uib(u), uib(swap16(u)));
                        float f = __uint_as_float(biu(t) & 0xFFFF0000u);
                        float wq = (q==0)?w.x:(q==1)?w.y:(q==2)?w.z:w.w;
                        raw = fmaf(fmaxf(f, 0.f), wq, raw);
                    }
                }
            }
            float ht = fminf(fmaxf(raw * (1.f/6.f) + 0.5f, 0.f), 1.f) - 0.5f;
            eta = fmaf(smem[OFF_OUTW + p], ht, eta);
        }
    }

    smem[OFF_PETA + tid] = eta;
    __syncthreads();
    if (tid < 32) {
        float esum = 0.f;
#pragma unroll
        for (int s = 0; s < 6; ++s) esum += smem[OFF_PETA + tid + 32 * s];
        esum += smem[OFF_MISC + 1];
        esum = fminf(fmaxf(esum, -20.f), 20.f);
        out[b] = __expf(esum) * exposure[b];
    }
}

extern "C" void kernel_launch(void* const* d_in, const int* in_sizes, int n_in,
                              void* d_out, int out_size)
{
    (void)in_sizes; (void)n_in; (void)out_size;
    size_t shmem = SMEM_U32 * 4;
    cudaFuncSetAttribute(pin_kernel, cudaFuncAttributeMaxDynamicSharedMemorySize,
                         (int)shmem);
    pin_kernel<<<NB / SPB, THREADS, shmem>>>(
        (const float*)d_in[0],  (const int*)d_in[1],   (const float*)d_in[2],
        (const float*)d_in[3],  (const float*)d_in[4], (const float*)d_in[5],
        (const float*)d_in[6],  (const float*)d_in[7], (const float*)d_in[8],
        (const float*)d_in[9],  (const float*)d_in[10],(const float*)d_in[11],
        (const float*)d_in[12], (const float*)d_in[13],(const float*)d_in[14],
        (const float*)d_in[15], (const float*)d_in[16],
        (float*)d_out);
}